// round 2
// baseline (speedup 1.0000x reference)
#include <cuda_runtime.h>
#include <math.h>

// ---------------------------------------------------------------------------
// Scratch (device globals — allocation-free per harness rules)
// ---------------------------------------------------------------------------
#define MAXN 20000
#define MAXD 1000
#define MAXDA 128

__device__ float g_sup [(size_t)MAXN * MAXD];   // 80 MB
__device__ float g_agg [(size_t)MAXN * MAXD];   // 80 MB
__device__ float g_supA[(size_t)MAXN * MAXDA];  // 10 MB
__device__ float g_aggA[(size_t)MAXN * MAXDA];  // 10 MB

// ---------------------------------------------------------------------------
// Zero kernel (vector stores, grid-stride)
// ---------------------------------------------------------------------------
__global__ void zero_kernel(float4* __restrict__ p, int n4) {
    int i = blockIdx.x * blockDim.x + threadIdx.x;
    int stride = gridDim.x * blockDim.x;
    float4 z = make_float4(0.f, 0.f, 0.f, 0.f);
    for (; i < n4; i += stride) p[i] = z;
}

// ---------------------------------------------------------------------------
// Tiled fp32 SGEMM: C[M,N] = op(A)[M,K] @ B[K,N], op = ReLU if RELU_A
// BM=BN=128, BK=8, 256 threads, 8x8 per-thread microtile,
// register double-buffering on the inner K loop.
// ---------------------------------------------------------------------------
template<bool RELU_A>
__global__ __launch_bounds__(256) void sgemm128(
    const float* __restrict__ A, const float* __restrict__ B,
    float* __restrict__ C, int M, int N, int K)
{
    __shared__ float As[8][128];
    __shared__ float Bs[8][128];

    const int tid = threadIdx.x;
    const int tx  = tid & 15;     // 16 col-threads
    const int ty  = tid >> 4;     // 16 row-threads
    const int row0 = blockIdx.y * 128;
    const int col0 = blockIdx.x * 128;

    float acc[8][8];
#pragma unroll
    for (int i = 0; i < 8; i++)
#pragma unroll
        for (int j = 0; j < 8; j++) acc[i][j] = 0.f;

    const int aRow = tid >> 1;          // 0..127
    const int aCol = (tid & 1) * 4;     // 0 or 4
    const int bRow = tid >> 5;          // 0..7
    const int bCol = (tid & 31) * 4;    // 0..124

    for (int k0 = 0; k0 < K; k0 += 8) {
        // ---- load A tile (transposed into As[k][m]) ----
        {
            int gr = row0 + aRow;
            int gk = k0 + aCol;
            float4 a = make_float4(0.f, 0.f, 0.f, 0.f);
            if (gr < M) {
                if (gk + 3 < K) {
                    a = *reinterpret_cast<const float4*>(A + (size_t)gr * K + gk);
                } else {
                    float t0 = (gk + 0 < K) ? A[(size_t)gr * K + gk + 0] : 0.f;
                    float t1 = (gk + 1 < K) ? A[(size_t)gr * K + gk + 1] : 0.f;
                    float t2 = (gk + 2 < K) ? A[(size_t)gr * K + gk + 2] : 0.f;
                    float t3 = (gk + 3 < K) ? A[(size_t)gr * K + gk + 3] : 0.f;
                    a = make_float4(t0, t1, t2, t3);
                }
            }
            if (RELU_A) {
                a.x = fmaxf(a.x, 0.f); a.y = fmaxf(a.y, 0.f);
                a.z = fmaxf(a.z, 0.f); a.w = fmaxf(a.w, 0.f);
            }
            As[aCol + 0][aRow] = a.x;
            As[aCol + 1][aRow] = a.y;
            As[aCol + 2][aRow] = a.z;
            As[aCol + 3][aRow] = a.w;
        }
        // ---- load B tile ----
        {
            int gk = k0 + bRow;
            int gc = col0 + bCol;
            float4 b = make_float4(0.f, 0.f, 0.f, 0.f);
            if (gk < K) {
                if (gc + 3 < N) {
                    b = *reinterpret_cast<const float4*>(B + (size_t)gk * N + gc);
                } else {
                    float t0 = (gc + 0 < N) ? B[(size_t)gk * N + gc + 0] : 0.f;
                    float t1 = (gc + 1 < N) ? B[(size_t)gk * N + gc + 1] : 0.f;
                    float t2 = (gc + 2 < N) ? B[(size_t)gk * N + gc + 2] : 0.f;
                    float t3 = (gc + 3 < N) ? B[(size_t)gk * N + gc + 3] : 0.f;
                    b = make_float4(t0, t1, t2, t3);
                }
            }
            *reinterpret_cast<float4*>(&Bs[bRow][bCol]) = b;
        }
        __syncthreads();

        // ---- inner product with register double-buffering ----
        float ar[2][8], br[2][8];
#pragma unroll
        for (int i = 0; i < 8; i++) ar[0][i] = As[0][ty * 8 + i];
#pragma unroll
        for (int j = 0; j < 8; j++) br[0][j] = Bs[0][tx * 8 + j];

#pragma unroll
        for (int kk = 0; kk < 8; kk++) {
            int cur = kk & 1, nxt = cur ^ 1;
            if (kk < 7) {
#pragma unroll
                for (int i = 0; i < 8; i++) ar[nxt][i] = As[kk + 1][ty * 8 + i];
#pragma unroll
                for (int j = 0; j < 8; j++) br[nxt][j] = Bs[kk + 1][tx * 8 + j];
            }
#pragma unroll
            for (int i = 0; i < 8; i++)
#pragma unroll
                for (int j = 0; j < 8; j++)
                    acc[i][j] += ar[cur][i] * br[cur][j];
        }
        __syncthreads();
    }

    // ---- store ----
#pragma unroll
    for (int i = 0; i < 8; i++) {
        int r = row0 + ty * 8 + i;
        if (r >= M) continue;
#pragma unroll
        for (int j = 0; j < 8; j += 4) {
            int c = col0 + tx * 8 + j;
            if (c + 3 < N) {
                *reinterpret_cast<float4*>(C + (size_t)r * N + c) =
                    make_float4(acc[i][j], acc[i][j+1], acc[i][j+2], acc[i][j+3]);
            } else {
                for (int jj = 0; jj < 4; jj++)
                    if (c + jj < N) C[(size_t)r * N + c + jj] = acc[i][j + jj];
            }
        }
    }
}

// ---------------------------------------------------------------------------
// SpMM (COO, atomic scatter):  out[row[e], :] += vals[e] * sup[col[e], :]
// Wide variant: one block per edge, D=1000 -> 250 float4, 256 threads
// ---------------------------------------------------------------------------
__global__ __launch_bounds__(256) void spmm_wide(
    const int* __restrict__ row, const int* __restrict__ col,
    const float* __restrict__ vals, const float* __restrict__ sup,
    float* __restrict__ out, int D)
{
    int e = blockIdx.x;
    int r = __ldg(row + e);
    int c = __ldg(col + e);
    float v = __ldg(vals + e);
    const float4* s = reinterpret_cast<const float4*>(sup + (size_t)c * D);
    float* o = out + (size_t)r * D;
    int nd4 = D >> 2;
    for (int t = threadIdx.x; t < nd4; t += blockDim.x) {
        float4 x = __ldg(s + t);
        atomicAdd(o + 4 * t + 0, v * x.x);
        atomicAdd(o + 4 * t + 1, v * x.y);
        atomicAdd(o + 4 * t + 2, v * x.z);
        atomicAdd(o + 4 * t + 3, v * x.w);
    }
}

// Narrow variant: one warp per edge (D=100 -> 25 float4 per edge)
__global__ __launch_bounds__(256) void spmm_narrow(
    const int* __restrict__ row, const int* __restrict__ col,
    const float* __restrict__ vals, const float* __restrict__ sup,
    float* __restrict__ out, int D, int E)
{
    int e = blockIdx.x * (blockDim.x >> 5) + (threadIdx.x >> 5);
    if (e >= E) return;
    int lane = threadIdx.x & 31;
    int r = __ldg(row + e);
    int c = __ldg(col + e);
    float v = __ldg(vals + e);
    const float4* s = reinterpret_cast<const float4*>(sup + (size_t)c * D);
    float* o = out + (size_t)r * D;
    int nd4 = D >> 2;
    for (int t = lane; t < nd4; t += 32) {
        float4 x = __ldg(s + t);
        atomicAdd(o + 4 * t + 0, v * x.x);
        atomicAdd(o + 4 * t + 1, v * x.y);
        atomicAdd(o + 4 * t + 2, v * x.z);
        atomicAdd(o + 4 * t + 3, v * x.w);
    }
}

// ---------------------------------------------------------------------------
// Fused relu + row L2-normalize
// ---------------------------------------------------------------------------
__global__ __launch_bounds__(256) void l2norm_relu(
    const float* __restrict__ in, float* __restrict__ out, int D)
{
    int r = blockIdx.x;
    const float* x = in + (size_t)r * D;
    float* o = out + (size_t)r * D;

    float s = 0.f;
    for (int t = threadIdx.x; t < D; t += blockDim.x) {
        float v = fmaxf(x[t], 0.f);
        s += v * v;
    }
#pragma unroll
    for (int off = 16; off > 0; off >>= 1)
        s += __shfl_xor_sync(0xFFFFFFFFu, s, off);
    __shared__ float red[8];
    int wid = threadIdx.x >> 5;
    if ((threadIdx.x & 31) == 0) red[wid] = s;
    __syncthreads();
    if (threadIdx.x < 8) {
        float t = red[threadIdx.x];
#pragma unroll
        for (int off = 4; off > 0; off >>= 1)
            t += __shfl_xor_sync(0xFFu, t, off);
        if (threadIdx.x == 0) red[0] = t;
    }
    __syncthreads();
    float inv = 1.f / fmaxf(sqrtf(red[0]), 1e-12f);
    for (int t = threadIdx.x; t < D; t += blockDim.x)
        o[t] = fmaxf(x[t], 0.f) * inv;
}

// Elementwise relu copy (attr branch output)
__global__ void relu_copy(const float* __restrict__ in, float* __restrict__ out, int n) {
    int i = blockIdx.x * blockDim.x + threadIdx.x;
    int stride = gridDim.x * blockDim.x;
    for (; i < n; i += stride) out[i] = fmaxf(in[i], 0.f);
}

// ---------------------------------------------------------------------------
// Host-side pipeline
// ---------------------------------------------------------------------------
static inline int cdiv(int a, int b) { return (a + b - 1) / b; }
static inline int isqrt_i(int v) { return (int)floor(sqrt((double)v) + 0.5); }

static void run_gemm(const float* A, const float* B, float* C,
                     int M, int N, int K, bool reluA)
{
    dim3 grid(cdiv(N, 128), cdiv(M, 128));
    if (reluA) sgemm128<true ><<<grid, 256>>>(A, B, C, M, N, K);
    else       sgemm128<false><<<grid, 256>>>(A, B, C, M, N, K);
}

static void zero_buf(float* p, size_t n) {
    int n4 = (int)(n / 4);
    zero_kernel<<<1024, 256>>>(reinterpret_cast<float4*>(p), n4);
}

extern "C" void kernel_launch(void* const* d_in, const int* in_sizes, int n_in,
                              void* d_out, int out_size)
{
    const float* emb_sr  = (const float*)d_in[0];
    const float* emb_tg  = (const float*)d_in[1];
    const float* attr_sr = (const float*)d_in[2];
    const float* attr_tg = (const float*)d_in[3];
    const int*   row_sr  = (const int*)  d_in[4];
    const int*   col_sr  = (const int*)  d_in[5];
    const float* vals_sr = (const float*)d_in[6];
    const int*   row_tg  = (const int*)  d_in[7];
    const int*   col_tg  = (const int*)  d_in[8];
    const float* vals_tg = (const float*)d_in[9];
    const float* W_s0    = (const float*)d_in[10];
    const float* W_s1    = (const float*)d_in[11];
    const float* W_a11   = (const float*)d_in[12];
    const float* W_a12   = (const float*)d_in[13];
    const float* W_a2    = (const float*)d_in[14];

    const int D  = isqrt_i(in_sizes[10]);          // 1000
    const int Da = isqrt_i(in_sizes[14]);          // 100
    const int A  = in_sizes[12] / Da;              // 1000
    const int N  = in_sizes[0] / D;                // 20000
    const int M  = in_sizes[1] / D;                // 20000
    const int E1 = in_sizes[4];                    // 160000
    const int E2 = in_sizes[7];

    float* sup;  cudaGetSymbolAddress((void**)&sup,  g_sup);
    float* agg;  cudaGetSymbolAddress((void**)&agg,  g_agg);
    float* supA; cudaGetSymbolAddress((void**)&supA, g_supA);
    float* aggA; cudaGetSymbolAddress((void**)&aggA, g_aggA);

    float* out = (float*)d_out;
    float* out_sr  = out;
    float* out_tg  = out + (size_t)N * D;
    float* out_sra = out + (size_t)(N + M) * D;
    float* out_tga = out_sra + (size_t)N * Da;

    // ---------------- structural branch (shared weights W_s0, W_s1) --------
    for (int g = 0; g < 2; g++) {
        const float* emb  = g ? emb_tg : emb_sr;
        const int*   row  = g ? row_tg : row_sr;
        const int*   col  = g ? col_tg : col_sr;
        const float* vals = g ? vals_tg : vals_sr;
        const int    E    = g ? E2 : E1;
        const int    Nn   = g ? M : N;
        float*       op   = g ? out_tg : out_sr;

        // layer 1
        run_gemm(emb, W_s0, sup, Nn, D, D, false);
        zero_buf(agg, (size_t)Nn * D);
        spmm_wide<<<E, 256>>>(row, col, vals, sup, agg, D);
        // layer 2 (relu fused into A read)
        run_gemm(agg, W_s1, sup, Nn, D, D, true);
        zero_buf(agg, (size_t)Nn * D);
        spmm_wide<<<E, 256>>>(row, col, vals, sup, agg, D);
        // relu + l2norm to output
        l2norm_relu<<<Nn, 256>>>(agg, op, D);
    }

    // ---------------- attribute branch ------------------------------------
    for (int g = 0; g < 2; g++) {
        const float* attr = g ? attr_tg : attr_sr;
        const float* Wa1  = g ? W_a12 : W_a11;
        const int*   row  = g ? row_tg : row_sr;
        const int*   col  = g ? col_tg : col_sr;
        const float* vals = g ? vals_tg : vals_sr;
        const int    E    = g ? E2 : E1;
        const int    Nn   = g ? M : N;
        float*       op   = g ? out_tga : out_sra;

        // layer 1: attr[Nn,A] @ Wa1[A,Da]
        run_gemm(attr, Wa1, supA, Nn, Da, A, false);
        zero_buf(aggA, (size_t)Nn * Da);
        spmm_narrow<<<cdiv(E, 8), 256>>>(row, col, vals, supA, aggA, Da, E);
        // layer 2: relu(agg) @ W_a2[Da,Da]
        run_gemm(aggA, W_a2, supA, Nn, Da, Da, true);
        zero_buf(aggA, (size_t)Nn * Da);
        spmm_narrow<<<cdiv(E, 8), 256>>>(row, col, vals, supA, aggA, Da, E);
        // final relu to output
        relu_copy<<<1024, 256>>>(aggA, op, Nn * Da);
    }
}

// round 6
// speedup vs baseline: 1.1590x; 1.1590x over previous
#include <cuda_runtime.h>
#include <math.h>
#include <stdint.h>

// ===========================================================================
// Scratch (device globals — allocation-free per harness rules)
// ===========================================================================
#define MAXN 20000
#define MAXD 1000
#define MAXDA 128

__device__ float g_sup [(size_t)MAXN * MAXD];   // 80 MB
__device__ float g_agg [(size_t)MAXN * MAXD];   // 80 MB
__device__ float g_supA[(size_t)MAXN * MAXDA];  // 10 MB
__device__ float g_aggA[(size_t)MAXN * MAXDA];  // 10 MB

// ===========================================================================
// Helpers
// ===========================================================================
// tf32 round-to-nearest (value kept in fp32 container, low 13 mantissa bits 0)
__device__ __forceinline__ float tf32_round(float x) {
    uint32_t u;
    asm("cvt.rna.tf32.f32 %0, %1;" : "=r"(u) : "f"(x));
    return __uint_as_float(u);
}

__device__ __forceinline__ void mma_tf32(float* c, const uint32_t* a, const uint32_t* b) {
    asm volatile(
        "mma.sync.aligned.m16n8k8.row.col.f32.tf32.tf32.f32 "
        "{%0,%1,%2,%3}, {%4,%5,%6,%7}, {%8,%9}, {%0,%1,%2,%3};"
        : "+f"(c[0]), "+f"(c[1]), "+f"(c[2]), "+f"(c[3])
        : "r"(a[0]), "r"(a[1]), "r"(a[2]), "r"(a[3]),
          "r"(b[0]), "r"(b[1]));
}

__device__ __forceinline__ float4 ldg4_guard(const float* __restrict__ p,
                                             int r, int c, int R, int C) {
    float4 v = make_float4(0.f, 0.f, 0.f, 0.f);
    if (r < R) {
        if (c + 3 < C) {
            v = *reinterpret_cast<const float4*>(p + (size_t)r * C + c);
        } else {
            if (c + 0 < C) v.x = p[(size_t)r * C + c + 0];
            if (c + 1 < C) v.y = p[(size_t)r * C + c + 1];
            if (c + 2 < C) v.z = p[(size_t)r * C + c + 2];
            if (c + 3 < C) v.w = p[(size_t)r * C + c + 3];
        }
    }
    return v;
}

// ===========================================================================
// Warp-MMA TF32x2-split GEMM:  C[M,N] = op(A)[M,K] @ B[K,N]
//   op = ReLU if RELU_A.  Block 128x128, BK=16, 256 threads,
//   8 warps (2x4), warp tile 64x32, mma.m16n8k8.tf32,
//   products: Ah*Bh + Ah*Bl + Al*Bh  (rel err ~2^-22).
// ===========================================================================
#define SM_STRIDE 132   // floats; makes fragment LDS bank-conflict-free

template<bool RELU_A>
__global__ __launch_bounds__(256)
void gemm_mma(const float* __restrict__ A, const float* __restrict__ B,
              float* __restrict__ C, int M, int N, int K)
{
    __shared__ float Ah[16][SM_STRIDE], Al[16][SM_STRIDE];
    __shared__ float Bh[16][SM_STRIDE], Bl[16][SM_STRIDE];

    const int tid  = threadIdx.x;
    const int wid  = tid >> 5;
    const int lane = tid & 31;
    const int g    = lane >> 2;          // groupID 0..7
    const int tig  = lane & 3;           // thread-in-group 0..3
    const int warp_m = wid >> 2;         // 0..1
    const int warp_n = wid & 3;          // 0..3
    const int m0 = blockIdx.y * 128;
    const int n0 = blockIdx.x * 128;

    // loader mappings
    const int ar  = tid >> 1;            // A tile row 0..127
    const int akq = (tid & 1) * 8;       // A k-offset 0/8
    const int bkr = tid >> 4;            // B tile k-row 0..15
    const int bnq = (tid & 15) * 8;      // B n-offset 0..120

    float acc[4][4][4];
#pragma unroll
    for (int i = 0; i < 4; i++)
#pragma unroll
        for (int j = 0; j < 4; j++)
#pragma unroll
            for (int q = 0; q < 4; q++) acc[i][j][q] = 0.f;

    const int nkt = (K + 15) >> 4;

    float4 aR0, aR1, bR0, bR1;
    // prefetch tile 0
    aR0 = ldg4_guard(A, m0 + ar, akq,          M, K);
    aR1 = ldg4_guard(A, m0 + ar, akq + 4,      M, K);
    bR0 = ldg4_guard(B, bkr,     n0 + bnq,     K, N);
    bR1 = ldg4_guard(B, bkr,     n0 + bnq + 4, K, N);

    for (int kt = 0; kt < nkt; kt++) {
        // ---- split + store current tile to smem ----
        {
            float av[8] = {aR0.x, aR0.y, aR0.z, aR0.w, aR1.x, aR1.y, aR1.z, aR1.w};
#pragma unroll
            for (int j = 0; j < 8; j++) {
                float x = RELU_A ? fmaxf(av[j], 0.f) : av[j];
                float h = tf32_round(x);
                Ah[akq + j][ar] = h;
                Al[akq + j][ar] = x - h;
            }
            float bv[8] = {bR0.x, bR0.y, bR0.z, bR0.w, bR1.x, bR1.y, bR1.z, bR1.w};
            float hv[8], lv[8];
#pragma unroll
            for (int j = 0; j < 8; j++) {
                hv[j] = tf32_round(bv[j]);
                lv[j] = bv[j] - hv[j];
            }
            *reinterpret_cast<float4*>(&Bh[bkr][bnq + 0]) = make_float4(hv[0], hv[1], hv[2], hv[3]);
            *reinterpret_cast<float4*>(&Bh[bkr][bnq + 4]) = make_float4(hv[4], hv[5], hv[6], hv[7]);
            *reinterpret_cast<float4*>(&Bl[bkr][bnq + 0]) = make_float4(lv[0], lv[1], lv[2], lv[3]);
            *reinterpret_cast<float4*>(&Bl[bkr][bnq + 4]) = make_float4(lv[4], lv[5], lv[6], lv[7]);
        }
        __syncthreads();

        // ---- prefetch next tile (overlaps with MMA below) ----
        if (kt + 1 < nkt) {
            const int kb = (kt + 1) * 16;
            aR0 = ldg4_guard(A, m0 + ar, kb + akq,          M, K);
            aR1 = ldg4_guard(A, m0 + ar, kb + akq + 4,      M, K);
            bR0 = ldg4_guard(B, kb + bkr, n0 + bnq,         K, N);
            bR1 = ldg4_guard(B, kb + bkr, n0 + bnq + 4,     K, N);
        }

        // ---- MMA over the two k=8 steps ----
#pragma unroll
        for (int ks = 0; ks < 2; ks++) {
            const int kk = ks * 8;
            uint32_t ah[4][4], al[4][4], bh[4][2], bl[4][2];
#pragma unroll
            for (int mi = 0; mi < 4; mi++) {
                const int m = warp_m * 64 + mi * 16 + g;
                ah[mi][0] = __float_as_uint(Ah[kk + tig    ][m    ]);
                ah[mi][1] = __float_as_uint(Ah[kk + tig    ][m + 8]);
                ah[mi][2] = __float_as_uint(Ah[kk + tig + 4][m    ]);
                ah[mi][3] = __float_as_uint(Ah[kk + tig + 4][m + 8]);
                al[mi][0] = __float_as_uint(Al[kk + tig    ][m    ]);
                al[mi][1] = __float_as_uint(Al[kk + tig    ][m + 8]);
                al[mi][2] = __float_as_uint(Al[kk + tig + 4][m    ]);
                al[mi][3] = __float_as_uint(Al[kk + tig + 4][m + 8]);
            }
#pragma unroll
            for (int ni = 0; ni < 4; ni++) {
                const int n = warp_n * 32 + ni * 8 + g;
                bh[ni][0] = __float_as_uint(Bh[kk + tig    ][n]);
                bh[ni][1] = __float_as_uint(Bh[kk + tig + 4][n]);
                bl[ni][0] = __float_as_uint(Bl[kk + tig    ][n]);
                bl[ni][1] = __float_as_uint(Bl[kk + tig + 4][n]);
            }
#pragma unroll
            for (int mi = 0; mi < 4; mi++)
#pragma unroll
                for (int ni = 0; ni < 4; ni++) {
                    mma_tf32(acc[mi][ni], ah[mi], bh[ni]);
                    mma_tf32(acc[mi][ni], ah[mi], bl[ni]);
                    mma_tf32(acc[mi][ni], al[mi], bh[ni]);
                }
        }
        __syncthreads();
    }

    // ---- epilogue ----
#pragma unroll
    for (int mi = 0; mi < 4; mi++) {
#pragma unroll
        for (int ni = 0; ni < 4; ni++) {
            const int r  = m0 + warp_m * 64 + mi * 16 + g;
            const int cc = n0 + warp_n * 32 + ni * 8 + 2 * tig;
            if (cc + 1 < N) {
                if (r < M)
                    *reinterpret_cast<float2*>(C + (size_t)r * N + cc) =
                        make_float2(acc[mi][ni][0], acc[mi][ni][1]);
                if (r + 8 < M)
                    *reinterpret_cast<float2*>(C + (size_t)(r + 8) * N + cc) =
                        make_float2(acc[mi][ni][2], acc[mi][ni][3]);
            } else if (cc < N) {
                if (r < M)     C[(size_t)r * N + cc]       = acc[mi][ni][0];
                if (r + 8 < M) C[(size_t)(r + 8) * N + cc] = acc[mi][ni][2];
            }
        }
    }
}

// ===========================================================================
// Zero kernel (vector stores, grid-stride)
// ===========================================================================
__global__ void zero_kernel(float4* __restrict__ p, int n4) {
    int i = blockIdx.x * blockDim.x + threadIdx.x;
    int stride = gridDim.x * blockDim.x;
    float4 z = make_float4(0.f, 0.f, 0.f, 0.f);
    for (; i < n4; i += stride) p[i] = z;
}

// ===========================================================================
// SpMM (COO, atomic scatter):  out[row[e], :] += vals[e] * sup[col[e], :]
// ===========================================================================
__global__ __launch_bounds__(256) void spmm_wide(
    const int* __restrict__ row, const int* __restrict__ col,
    const float* __restrict__ vals, const float* __restrict__ sup,
    float* __restrict__ out, int D)
{
    int e = blockIdx.x;
    int r = __ldg(row + e);
    int c = __ldg(col + e);
    float v = __ldg(vals + e);
    const float4* s = reinterpret_cast<const float4*>(sup + (size_t)c * D);
    float* o = out + (size_t)r * D;
    int nd4 = D >> 2;
    for (int t = threadIdx.x; t < nd4; t += blockDim.x) {
        float4 x = __ldg(s + t);
        atomicAdd(o + 4 * t + 0, v * x.x);
        atomicAdd(o + 4 * t + 1, v * x.y);
        atomicAdd(o + 4 * t + 2, v * x.z);
        atomicAdd(o + 4 * t + 3, v * x.w);
    }
}

__global__ __launch_bounds__(256) void spmm_narrow(
    const int* __restrict__ row, const int* __restrict__ col,
    const float* __restrict__ vals, const float* __restrict__ sup,
    float* __restrict__ out, int D, int E)
{
    int e = blockIdx.x * (blockDim.x >> 5) + (threadIdx.x >> 5);
    if (e >= E) return;
    int lane = threadIdx.x & 31;
    int r = __ldg(row + e);
    int c = __ldg(col + e);
    float v = __ldg(vals + e);
    const float4* s = reinterpret_cast<const float4*>(sup + (size_t)c * D);
    float* o = out + (size_t)r * D;
    int nd4 = D >> 2;
    for (int t = lane; t < nd4; t += 32) {
        float4 x = __ldg(s + t);
        atomicAdd(o + 4 * t + 0, v * x.x);
        atomicAdd(o + 4 * t + 1, v * x.y);
        atomicAdd(o + 4 * t + 2, v * x.z);
        atomicAdd(o + 4 * t + 3, v * x.w);
    }
}

// ===========================================================================
// Fused relu + row L2-normalize
// ===========================================================================
__global__ __launch_bounds__(256) void l2norm_relu(
    const float* __restrict__ in, float* __restrict__ out, int D)
{
    int r = blockIdx.x;
    const float* x = in + (size_t)r * D;
    float* o = out + (size_t)r * D;

    float s = 0.f;
    for (int t = threadIdx.x; t < D; t += blockDim.x) {
        float v = fmaxf(x[t], 0.f);
        s += v * v;
    }
#pragma unroll
    for (int off = 16; off > 0; off >>= 1)
        s += __shfl_xor_sync(0xFFFFFFFFu, s, off);
    __shared__ float red[8];
    int wid = threadIdx.x >> 5;
    if ((threadIdx.x & 31) == 0) red[wid] = s;
    __syncthreads();
    if (threadIdx.x < 8) {
        float t = red[threadIdx.x];
#pragma unroll
        for (int off = 4; off > 0; off >>= 1)
            t += __shfl_xor_sync(0xFFu, t, off);
        if (threadIdx.x == 0) red[0] = t;
    }
    __syncthreads();
    float inv = 1.f / fmaxf(sqrtf(red[0]), 1e-12f);
    for (int t = threadIdx.x; t < D; t += blockDim.x)
        o[t] = fmaxf(x[t], 0.f) * inv;
}

__global__ void relu_copy(const float* __restrict__ in, float* __restrict__ out, int n) {
    int i = blockIdx.x * blockDim.x + threadIdx.x;
    int stride = gridDim.x * blockDim.x;
    for (; i < n; i += stride) out[i] = fmaxf(in[i], 0.f);
}

// ===========================================================================
// Host-side pipeline
// ===========================================================================
static inline int cdiv(int a, int b) { return (a + b - 1) / b; }
static inline int isqrt_i(int v) { return (int)floor(sqrt((double)v) + 0.5); }

static void run_gemm(const float* A, const float* B, float* C,
                     int M, int N, int K, bool reluA)
{
    dim3 grid(cdiv(N, 128), cdiv(M, 128));
    if (reluA) gemm_mma<true ><<<grid, 256>>>(A, B, C, M, N, K);
    else       gemm_mma<false><<<grid, 256>>>(A, B, C, M, N, K);
}

static void zero_buf(float* p, size_t n) {
    int n4 = (int)(n / 4);
    zero_kernel<<<1024, 256>>>(reinterpret_cast<float4*>(p), n4);
}

extern "C" void kernel_launch(void* const* d_in, const int* in_sizes, int n_in,
                              void* d_out, int out_size)
{
    const float* emb_sr  = (const float*)d_in[0];
    const float* emb_tg  = (const float*)d_in[1];
    const float* attr_sr = (const float*)d_in[2];
    const float* attr_tg = (const float*)d_in[3];
    const int*   row_sr  = (const int*)  d_in[4];
    const int*   col_sr  = (const int*)  d_in[5];
    const float* vals_sr = (const float*)d_in[6];
    const int*   row_tg  = (const int*)  d_in[7];
    const int*   col_tg  = (const int*)  d_in[8];
    const float* vals_tg = (const float*)d_in[9];
    const float* W_s0    = (const float*)d_in[10];
    const float* W_s1    = (const float*)d_in[11];
    const float* W_a11   = (const float*)d_in[12];
    const float* W_a12   = (const float*)d_in[13];
    const float* W_a2    = (const float*)d_in[14];

    const int D  = isqrt_i(in_sizes[10]);          // 1000
    const int Da = isqrt_i(in_sizes[14]);          // 100
    const int A  = in_sizes[12] / Da;              // 1000
    const int N  = in_sizes[0] / D;                // 20000
    const int M  = in_sizes[1] / D;                // 20000
    const int E1 = in_sizes[4];                    // 160000
    const int E2 = in_sizes[7];

    float* sup;  cudaGetSymbolAddress((void**)&sup,  g_sup);
    float* agg;  cudaGetSymbolAddress((void**)&agg,  g_agg);
    float* supA; cudaGetSymbolAddress((void**)&supA, g_supA);
    float* aggA; cudaGetSymbolAddress((void**)&aggA, g_aggA);

    float* out = (float*)d_out;
    float* out_sr  = out;
    float* out_tg  = out + (size_t)N * D;
    float* out_sra = out + (size_t)(N + M) * D;
    float* out_tga = out_sra + (size_t)N * Da;

    // ---------------- structural branch (shared weights W_s0, W_s1) --------
    for (int g = 0; g < 2; g++) {
        const float* emb  = g ? emb_tg : emb_sr;
        const int*   row  = g ? row_tg : row_sr;
        const int*   col  = g ? col_tg : col_sr;
        const float* vals = g ? vals_tg : vals_sr;
        const int    E    = g ? E2 : E1;
        const int    Nn   = g ? M : N;
        float*       op   = g ? out_tg : out_sr;

        // layer 1
        run_gemm(emb, W_s0, sup, Nn, D, D, false);
        zero_buf(agg, (size_t)Nn * D);
        spmm_wide<<<E, 256>>>(row, col, vals, sup, agg, D);
        // layer 2 (relu fused into A-tile load)
        run_gemm(agg, W_s1, sup, Nn, D, D, true);
        zero_buf(agg, (size_t)Nn * D);
        spmm_wide<<<E, 256>>>(row, col, vals, sup, agg, D);
        // relu + l2norm to output
        l2norm_relu<<<Nn, 256>>>(agg, op, D);
    }

    // ---------------- attribute branch ------------------------------------
    for (int g = 0; g < 2; g++) {
        const float* attr = g ? attr_tg : attr_sr;
        const float* Wa1  = g ? W_a12 : W_a11;
        const int*   row  = g ? row_tg : row_sr;
        const int*   col  = g ? col_tg : col_sr;
        const float* vals = g ? vals_tg : vals_sr;
        const int    E    = g ? E2 : E1;
        const int    Nn   = g ? M : N;
        float*       op   = g ? out_tga : out_sra;

        // layer 1: attr[Nn,A] @ Wa1[A,Da]
        run_gemm(attr, Wa1, supA, Nn, Da, A, false);
        zero_buf(aggA, (size_t)Nn * Da);
        spmm_narrow<<<cdiv(E, 8), 256>>>(row, col, vals, supA, aggA, Da, E);
        // layer 2: relu(agg) @ W_a2[Da,Da]
        run_gemm(aggA, W_a2, supA, Nn, Da, Da, true);
        zero_buf(aggA, (size_t)Nn * Da);
        spmm_narrow<<<cdiv(E, 8), 256>>>(row, col, vals, supA, aggA, Da, E);
        // final relu to output
        relu_copy<<<1024, 256>>>(aggA, op, Nn * Da);
    }
}

// round 8
// speedup vs baseline: 1.4673x; 1.2660x over previous
#include <cuda_runtime.h>
#include <math.h>
#include <stdint.h>

// ===========================================================================
// Scratch (device globals — allocation-free per harness rules)
// ===========================================================================
#define MAXN 20000
#define MAXD 1000
#define MAXDA 128

__device__ float g_sup [(size_t)MAXN * MAXD];   // 80 MB
__device__ float g_agg [(size_t)MAXN * MAXD];   // 80 MB
__device__ float g_supA[(size_t)MAXN * MAXDA];  // 10 MB
__device__ float g_aggA[(size_t)MAXN * MAXDA];  // 10 MB

// ===========================================================================
// Helpers
// ===========================================================================
__device__ __forceinline__ float tf32_round(float x) {
    uint32_t u;
    asm("cvt.rna.tf32.f32 %0, %1;" : "=r"(u) : "f"(x));
    return __uint_as_float(u);
}

__device__ __forceinline__ void mma_tf32(float* c, const uint32_t* a, const uint32_t* b) {
    asm volatile(
        "mma.sync.aligned.m16n8k8.row.col.f32.tf32.tf32.f32 "
        "{%0,%1,%2,%3}, {%4,%5,%6,%7}, {%8,%9}, {%0,%1,%2,%3};"
        : "+f"(c[0]), "+f"(c[1]), "+f"(c[2]), "+f"(c[3])
        : "r"(a[0]), "r"(a[1]), "r"(a[2]), "r"(a[3]),
          "r"(b[0]), "r"(b[1]));
}

__device__ __forceinline__ float4 ldg4_guard(const float* __restrict__ p,
                                             int r, int c, int R, int C) {
    float4 v = make_float4(0.f, 0.f, 0.f, 0.f);
    if (r < R) {
        if (c + 3 < C) {
            v = *reinterpret_cast<const float4*>(p + (size_t)r * C + c);
        } else {
            if (c + 0 < C) v.x = p[(size_t)r * C + c + 0];
            if (c + 1 < C) v.y = p[(size_t)r * C + c + 1];
            if (c + 2 < C) v.z = p[(size_t)r * C + c + 2];
            if (c + 3 < C) v.w = p[(size_t)r * C + c + 3];
        }
    }
    return v;
}

// vectorized fire-and-forget global reduction (PTX ISA 8.1, sm_90+ baseline)
__device__ __forceinline__ void red_add_v4(float* p, float a, float b, float c, float d) {
    asm volatile("red.global.add.v4.f32 [%0], {%1, %2, %3, %4};"
                 :: "l"(p), "f"(a), "f"(b), "f"(c), "f"(d) : "memory");
}

// ===========================================================================
// Warp-MMA TF32x2-split GEMM:  C[M,N] = op(A)[M,K] @ B[K,N]
//   Block 128x128, BK=16, 256 threads, 8 warps (2x4), warp tile 64x32.
//   Raw fp32 tiles in smem (double-buffered); tf32 hi/lo split happens at
//   fragment-load time. Products: Ah*Bh + Ah*Bl + Al*Bh (rel err ~2^-22).
// ===========================================================================
#define SM_STRIDE 132   // floats; makes fragment LDS bank-conflict-free

template<bool RELU_A>
__global__ __launch_bounds__(256)
void gemm_mma(const float* __restrict__ A, const float* __restrict__ B,
              float* __restrict__ C, int M, int N, int K)
{
    __shared__ float As[2][16][SM_STRIDE];
    __shared__ float Bs[2][16][SM_STRIDE];

    const int tid  = threadIdx.x;
    const int wid  = tid >> 5;
    const int lane = tid & 31;
    const int g    = lane >> 2;          // groupID 0..7
    const int tig  = lane & 3;           // thread-in-group 0..3
    const int warp_m = wid >> 2;         // 0..1
    const int warp_n = wid & 3;          // 0..3
    const int m0 = blockIdx.y * 128;
    const int n0 = blockIdx.x * 128;

    // loader mappings
    const int ar  = tid >> 1;            // A tile row 0..127
    const int akq = (tid & 1) * 8;       // A k-offset 0/8
    const int bkr = tid >> 4;            // B tile k-row 0..15
    const int bnq = (tid & 15) * 8;      // B n-offset 0..120

    float acc[4][4][4];
#pragma unroll
    for (int i = 0; i < 4; i++)
#pragma unroll
        for (int j = 0; j < 4; j++)
#pragma unroll
            for (int q = 0; q < 4; q++) acc[i][j][q] = 0.f;

    const int nkt = (K + 15) >> 4;

    float4 aR0, aR1, bR0, bR1;
    // load tile 0 and stage it
    aR0 = ldg4_guard(A, m0 + ar, akq,          M, K);
    aR1 = ldg4_guard(A, m0 + ar, akq + 4,      M, K);
    bR0 = ldg4_guard(B, bkr,     n0 + bnq,     K, N);
    bR1 = ldg4_guard(B, bkr,     n0 + bnq + 4, K, N);
    {
        float av[8] = {aR0.x, aR0.y, aR0.z, aR0.w, aR1.x, aR1.y, aR1.z, aR1.w};
#pragma unroll
        for (int j = 0; j < 8; j++)
            As[0][akq + j][ar] = RELU_A ? fmaxf(av[j], 0.f) : av[j];
        *reinterpret_cast<float4*>(&Bs[0][bkr][bnq + 0]) = bR0;
        *reinterpret_cast<float4*>(&Bs[0][bkr][bnq + 4]) = bR1;
    }
    __syncthreads();

    for (int kt = 0; kt < nkt; kt++) {
        const int cur = kt & 1;
        const bool more = (kt + 1 < nkt);

        // ---- issue global prefetch for tile kt+1 (overlaps MMA below) ----
        if (more) {
            const int kb = (kt + 1) * 16;
            aR0 = ldg4_guard(A, m0 + ar,  kb + akq,      M, K);
            aR1 = ldg4_guard(A, m0 + ar,  kb + akq + 4,  M, K);
            bR0 = ldg4_guard(B, kb + bkr, n0 + bnq,      K, N);
            bR1 = ldg4_guard(B, kb + bkr, n0 + bnq + 4,  K, N);
        }

        // ---- MMA over the two k=8 steps (split at fragment-load time) ----
#pragma unroll
        for (int ks = 0; ks < 2; ks++) {
            const int kk = ks * 8;
            uint32_t ah[4][4], al[4][4], bh[4][2], bl[4][2];
#pragma unroll
            for (int mi = 0; mi < 4; mi++) {
                const int m = warp_m * 64 + mi * 16 + g;
                float x0 = As[cur][kk + tig    ][m    ];
                float x1 = As[cur][kk + tig    ][m + 8];
                float x2 = As[cur][kk + tig + 4][m    ];
                float x3 = As[cur][kk + tig + 4][m + 8];
                float h0 = tf32_round(x0), h1 = tf32_round(x1);
                float h2 = tf32_round(x2), h3 = tf32_round(x3);
                ah[mi][0] = __float_as_uint(h0); al[mi][0] = __float_as_uint(x0 - h0);
                ah[mi][1] = __float_as_uint(h1); al[mi][1] = __float_as_uint(x1 - h1);
                ah[mi][2] = __float_as_uint(h2); al[mi][2] = __float_as_uint(x2 - h2);
                ah[mi][3] = __float_as_uint(h3); al[mi][3] = __float_as_uint(x3 - h3);
            }
#pragma unroll
            for (int ni = 0; ni < 4; ni++) {
                const int n = warp_n * 32 + ni * 8 + g;
                float y0 = Bs[cur][kk + tig    ][n];
                float y1 = Bs[cur][kk + tig + 4][n];
                float h0 = tf32_round(y0), h1 = tf32_round(y1);
                bh[ni][0] = __float_as_uint(h0); bl[ni][0] = __float_as_uint(y0 - h0);
                bh[ni][1] = __float_as_uint(h1); bl[ni][1] = __float_as_uint(y1 - h1);
            }
#pragma unroll
            for (int mi = 0; mi < 4; mi++)
#pragma unroll
                for (int ni = 0; ni < 4; ni++) {
                    mma_tf32(acc[mi][ni], ah[mi], bh[ni]);
                    mma_tf32(acc[mi][ni], ah[mi], bl[ni]);
                    mma_tf32(acc[mi][ni], al[mi], bh[ni]);
                }
        }

        // ---- stage tile kt+1 into the other buffer ----
        if (more) {
            const int nxt = cur ^ 1;
            float av[8] = {aR0.x, aR0.y, aR0.z, aR0.w, aR1.x, aR1.y, aR1.z, aR1.w};
#pragma unroll
            for (int j = 0; j < 8; j++)
                As[nxt][akq + j][ar] = RELU_A ? fmaxf(av[j], 0.f) : av[j];
            *reinterpret_cast<float4*>(&Bs[nxt][bkr][bnq + 0]) = bR0;
            *reinterpret_cast<float4*>(&Bs[nxt][bkr][bnq + 4]) = bR1;
        }
        __syncthreads();
    }

    // ---- epilogue ----
#pragma unroll
    for (int mi = 0; mi < 4; mi++) {
#pragma unroll
        for (int ni = 0; ni < 4; ni++) {
            const int r  = m0 + warp_m * 64 + mi * 16 + g;
            const int cc = n0 + warp_n * 32 + ni * 8 + 2 * tig;
            if (cc + 1 < N) {
                if (r < M)
                    *reinterpret_cast<float2*>(C + (size_t)r * N + cc) =
                        make_float2(acc[mi][ni][0], acc[mi][ni][1]);
                if (r + 8 < M)
                    *reinterpret_cast<float2*>(C + (size_t)(r + 8) * N + cc) =
                        make_float2(acc[mi][ni][2], acc[mi][ni][3]);
            } else if (cc < N) {
                if (r < M)     C[(size_t)r * N + cc]       = acc[mi][ni][0];
                if (r + 8 < M) C[(size_t)(r + 8) * N + cc] = acc[mi][ni][2];
            }
        }
    }
}

// ===========================================================================
// Zero kernel (vector stores, grid-stride)
// ===========================================================================
__global__ void zero_kernel(float4* __restrict__ p, int n4) {
    int i = blockIdx.x * blockDim.x + threadIdx.x;
    int stride = gridDim.x * blockDim.x;
    float4 z = make_float4(0.f, 0.f, 0.f, 0.f);
    for (; i < n4; i += stride) p[i] = z;
}

// ===========================================================================
// SpMM (COO, vector-red scatter):  out[row[e], :] += vals[e] * sup[col[e], :]
// ===========================================================================
__global__ __launch_bounds__(256) void spmm_wide(
    const int* __restrict__ row, const int* __restrict__ col,
    const float* __restrict__ vals, const float* __restrict__ sup,
    float* __restrict__ out, int D)
{
    int e = blockIdx.x;
    int r = __ldg(row + e);
    int c = __ldg(col + e);
    float v = __ldg(vals + e);
    const float4* s = reinterpret_cast<const float4*>(sup + (size_t)c * D);
    float* o = out + (size_t)r * D;
    int nd4 = D >> 2;
    for (int t = threadIdx.x; t < nd4; t += blockDim.x) {
        float4 x = __ldg(s + t);
        red_add_v4(o + 4 * t, v * x.x, v * x.y, v * x.z, v * x.w);
    }
}

__global__ __launch_bounds__(256) void spmm_narrow(
    const int* __restrict__ row, const int* __restrict__ col,
    const float* __restrict__ vals, const float* __restrict__ sup,
    float* __restrict__ out, int D, int E)
{
    int e = blockIdx.x * (blockDim.x >> 5) + (threadIdx.x >> 5);
    if (e >= E) return;
    int lane = threadIdx.x & 31;
    int r = __ldg(row + e);
    int c = __ldg(col + e);
    float v = __ldg(vals + e);
    const float4* s = reinterpret_cast<const float4*>(sup + (size_t)c * D);
    float* o = out + (size_t)r * D;
    int nd4 = D >> 2;
    for (int t = lane; t < nd4; t += 32) {
        float4 x = __ldg(s + t);
        red_add_v4(o + 4 * t, v * x.x, v * x.y, v * x.z, v * x.w);
    }
}

// ===========================================================================
// Fused relu + row L2-normalize
// ===========================================================================
__global__ __launch_bounds__(256) void l2norm_relu(
    const float* __restrict__ in, float* __restrict__ out, int D)
{
    int r = blockIdx.x;
    const float* x = in + (size_t)r * D;
    float* o = out + (size_t)r * D;

    float s = 0.f;
    for (int t = threadIdx.x; t < D; t += blockDim.x) {
        float v = fmaxf(x[t], 0.f);
        s += v * v;
    }
#pragma unroll
    for (int off = 16; off > 0; off >>= 1)
        s += __shfl_xor_sync(0xFFFFFFFFu, s, off);
    __shared__ float red[8];
    int wid = threadIdx.x >> 5;
    if ((threadIdx.x & 31) == 0) red[wid] = s;
    __syncthreads();
    if (threadIdx.x < 8) {
        float t = red[threadIdx.x];
#pragma unroll
        for (int off = 4; off > 0; off >>= 1)
            t += __shfl_xor_sync(0xFFu, t, off);
        if (threadIdx.x == 0) red[0] = t;
    }
    __syncthreads();
    float inv = 1.f / fmaxf(sqrtf(red[0]), 1e-12f);
    for (int t = threadIdx.x; t < D; t += blockDim.x)
        o[t] = fmaxf(x[t], 0.f) * inv;
}

__global__ void relu_copy(const float* __restrict__ in, float* __restrict__ out, int n) {
    int i = blockIdx.x * blockDim.x + threadIdx.x;
    int stride = gridDim.x * blockDim.x;
    for (; i < n; i += stride) out[i] = fmaxf(in[i], 0.f);
}

// ===========================================================================
// Host-side pipeline
// ===========================================================================
static inline int cdiv(int a, int b) { return (a + b - 1) / b; }
static inline int isqrt_i(int v) { return (int)floor(sqrt((double)v) + 0.5); }

static void run_gemm(const float* A, const float* B, float* C,
                     int M, int N, int K, bool reluA)
{
    dim3 grid(cdiv(N, 128), cdiv(M, 128));
    if (reluA) gemm_mma<true ><<<grid, 256>>>(A, B, C, M, N, K);
    else       gemm_mma<false><<<grid, 256>>>(A, B, C, M, N, K);
}

static void zero_buf(float* p, size_t n) {
    int n4 = (int)(n / 4);
    zero_kernel<<<1024, 256>>>(reinterpret_cast<float4*>(p), n4);
}

extern "C" void kernel_launch(void* const* d_in, const int* in_sizes, int n_in,
                              void* d_out, int out_size)
{
    const float* emb_sr  = (const float*)d_in[0];
    const float* emb_tg  = (const float*)d_in[1];
    const float* attr_sr = (const float*)d_in[2];
    const float* attr_tg = (const float*)d_in[3];
    const int*   row_sr  = (const int*)  d_in[4];
    const int*   col_sr  = (const int*)  d_in[5];
    const float* vals_sr = (const float*)d_in[6];
    const int*   row_tg  = (const int*)  d_in[7];
    const int*   col_tg  = (const int*)  d_in[8];
    const float* vals_tg = (const float*)d_in[9];
    const float* W_s0    = (const float*)d_in[10];
    const float* W_s1    = (const float*)d_in[11];
    const float* W_a11   = (const float*)d_in[12];
    const float* W_a12   = (const float*)d_in[13];
    const float* W_a2    = (const float*)d_in[14];

    const int D  = isqrt_i(in_sizes[10]);          // 1000
    const int Da = isqrt_i(in_sizes[14]);          // 100
    const int A  = in_sizes[12] / Da;              // 1000
    const int N  = in_sizes[0] / D;                // 20000
    const int M  = in_sizes[1] / D;                // 20000
    const int E1 = in_sizes[4];                    // 160000
    const int E2 = in_sizes[7];

    float* sup;  cudaGetSymbolAddress((void**)&sup,  g_sup);
    float* agg;  cudaGetSymbolAddress((void**)&agg,  g_agg);
    float* supA; cudaGetSymbolAddress((void**)&supA, g_supA);
    float* aggA; cudaGetSymbolAddress((void**)&aggA, g_aggA);

    float* out = (float*)d_out;
    float* out_sr  = out;
    float* out_tg  = out + (size_t)N * D;
    float* out_sra = out + (size_t)(N + M) * D;
    float* out_tga = out_sra + (size_t)N * Da;

    // ---------------- structural branch (shared weights W_s0, W_s1) --------
    for (int g = 0; g < 2; g++) {
        const float* emb  = g ? emb_tg : emb_sr;
        const int*   row  = g ? row_tg : row_sr;
        const int*   col  = g ? col_tg : col_sr;
        const float* vals = g ? vals_tg : vals_sr;
        const int    E    = g ? E2 : E1;
        const int    Nn   = g ? M : N;
        float*       op   = g ? out_tg : out_sr;

        // layer 1
        run_gemm(emb, W_s0, sup, Nn, D, D, false);
        zero_buf(agg, (size_t)Nn * D);
        spmm_wide<<<E, 256>>>(row, col, vals, sup, agg, D);
        // layer 2 (relu fused into A-tile load)
        run_gemm(agg, W_s1, sup, Nn, D, D, true);
        zero_buf(agg, (size_t)Nn * D);
        spmm_wide<<<E, 256>>>(row, col, vals, sup, agg, D);
        // relu + l2norm to output
        l2norm_relu<<<Nn, 256>>>(agg, op, D);
    }

    // ---------------- attribute branch ------------------------------------
    for (int g = 0; g < 2; g++) {
        const float* attr = g ? attr_tg : attr_sr;
        const float* Wa1  = g ? W_a12 : W_a11;
        const int*   row  = g ? row_tg : row_sr;
        const int*   col  = g ? col_tg : col_sr;
        const float* vals = g ? vals_tg : vals_sr;
        const int    E    = g ? E2 : E1;
        const int    Nn   = g ? M : N;
        float*       op   = g ? out_tga : out_sra;

        // layer 1: attr[Nn,A] @ Wa1[A,Da]
        run_gemm(attr, Wa1, supA, Nn, Da, A, false);
        zero_buf(aggA, (size_t)Nn * Da);
        spmm_narrow<<<cdiv(E, 8), 256>>>(row, col, vals, supA, aggA, Da, E);
        // layer 2: relu(agg) @ W_a2[Da,Da]
        run_gemm(aggA, W_a2, supA, Nn, Da, Da, true);
        zero_buf(aggA, (size_t)Nn * Da);
        spmm_narrow<<<cdiv(E, 8), 256>>>(row, col, vals, supA, aggA, Da, E);
        // final relu to output
        relu_copy<<<1024, 256>>>(aggA, op, Nn * Da);
    }
}

// round 9
// speedup vs baseline: 1.7880x; 1.2186x over previous
#include <cuda_runtime.h>
#include <math.h>
#include <stdint.h>

// ===========================================================================
// Scratch (device globals — allocation-free per harness rules)
// ===========================================================================
#define MAXN 20000
#define MAXD 1000
#define MAXDA 128

__device__ float g_sup [(size_t)MAXN * MAXD];   // 80 MB
__device__ float g_agg [(size_t)MAXN * MAXD];   // 80 MB
__device__ float g_supA[(size_t)MAXN * MAXDA];  // 10 MB
__device__ float g_aggA[(size_t)MAXN * MAXDA];  // 10 MB

// ===========================================================================
// Helpers
// ===========================================================================
// Truncation-based tf32 split: hi = x with low 13 mantissa bits zeroed (exact
// in tf32), lo = x - hi (exact fp32). HW tf32 MMA truncates operand low bits,
// so both terms are consumed exactly; dropped al*bl term ~2^-22 relative.
__device__ __forceinline__ uint32_t tf32_hi_bits(float x) {
    return __float_as_uint(x) & 0xFFFFE000u;
}

__device__ __forceinline__ void mma_tf32(float* c, const uint32_t* a, const uint32_t* b) {
    asm volatile(
        "mma.sync.aligned.m16n8k8.row.col.f32.tf32.tf32.f32 "
        "{%0,%1,%2,%3}, {%4,%5,%6,%7}, {%8,%9}, {%0,%1,%2,%3};"
        : "+f"(c[0]), "+f"(c[1]), "+f"(c[2]), "+f"(c[3])
        : "r"(a[0]), "r"(a[1]), "r"(a[2]), "r"(a[3]),
          "r"(b[0]), "r"(b[1]));
}

__device__ __forceinline__ float4 ldg4_guard(const float* __restrict__ p,
                                             int r, int c, int R, int C) {
    float4 v = make_float4(0.f, 0.f, 0.f, 0.f);
    if (r < R) {
        if (c + 3 < C) {
            v = *reinterpret_cast<const float4*>(p + (size_t)r * C + c);
        } else {
            if (c + 0 < C) v.x = p[(size_t)r * C + c + 0];
            if (c + 1 < C) v.y = p[(size_t)r * C + c + 1];
            if (c + 2 < C) v.z = p[(size_t)r * C + c + 2];
            if (c + 3 < C) v.w = p[(size_t)r * C + c + 3];
        }
    }
    return v;
}

// vectorized fire-and-forget global reduction (PTX ISA 8.1, sm_90+ baseline)
__device__ __forceinline__ void red_add_v4(float* p, float a, float b, float c, float d) {
    asm volatile("red.global.add.v4.f32 [%0], {%1, %2, %3, %4};"
                 :: "l"(p), "f"(a), "f"(b), "f"(c), "f"(d) : "memory");
}

// ===========================================================================
// Warp-MMA TF32x2-split GEMM:  C[M,N] = op(A)[M,K] @ B[K,N]
//   Block 128x128, BK=16, 256 threads, 8 warps (2x4), warp tile 64x32.
//   Raw fp32 tiles in smem (double-buffered); tf32 hi/lo split at fragment
//   load (mask+sub). Product-major MMA order (independent accumulators).
//   __launch_bounds__(256,2) -> 2 CTA/SM.
// ===========================================================================
#define SM_STRIDE 132   // floats; makes fragment LDS bank-conflict-free

template<bool RELU_A>
__global__ __launch_bounds__(256, 2)
void gemm_mma(const float* __restrict__ A, const float* __restrict__ B,
              float* __restrict__ C, int M, int N, int K)
{
    __shared__ float As[2][16][SM_STRIDE];
    __shared__ float Bs[2][16][SM_STRIDE];

    const int tid  = threadIdx.x;
    const int wid  = tid >> 5;
    const int lane = tid & 31;
    const int g    = lane >> 2;          // groupID 0..7
    const int tig  = lane & 3;           // thread-in-group 0..3
    const int warp_m = wid >> 2;         // 0..1
    const int warp_n = wid & 3;          // 0..3
    const int m0 = blockIdx.y * 128;
    const int n0 = blockIdx.x * 128;

    // loader mappings
    const int ar  = tid >> 1;            // A tile row 0..127
    const int akq = (tid & 1) * 8;       // A k-offset 0/8
    const int bkr = tid >> 4;            // B tile k-row 0..15
    const int bnq = (tid & 15) * 8;      // B n-offset 0..120

    float acc[4][4][4];
#pragma unroll
    for (int i = 0; i < 4; i++)
#pragma unroll
        for (int j = 0; j < 4; j++)
#pragma unroll
            for (int q = 0; q < 4; q++) acc[i][j][q] = 0.f;

    const int nkt = (K + 15) >> 4;

    float4 aR0, aR1, bR0, bR1;
    // load tile 0 and stage it
    aR0 = ldg4_guard(A, m0 + ar, akq,          M, K);
    aR1 = ldg4_guard(A, m0 + ar, akq + 4,      M, K);
    bR0 = ldg4_guard(B, bkr,     n0 + bnq,     K, N);
    bR1 = ldg4_guard(B, bkr,     n0 + bnq + 4, K, N);
    {
        float av[8] = {aR0.x, aR0.y, aR0.z, aR0.w, aR1.x, aR1.y, aR1.z, aR1.w};
#pragma unroll
        for (int j = 0; j < 8; j++)
            As[0][akq + j][ar] = RELU_A ? fmaxf(av[j], 0.f) : av[j];
        *reinterpret_cast<float4*>(&Bs[0][bkr][bnq + 0]) = bR0;
        *reinterpret_cast<float4*>(&Bs[0][bkr][bnq + 4]) = bR1;
    }
    __syncthreads();

    for (int kt = 0; kt < nkt; kt++) {
        const int cur = kt & 1;
        const bool more = (kt + 1 < nkt);

        // ---- issue global prefetch for tile kt+1 (overlaps MMA below) ----
        if (more) {
            const int kb = (kt + 1) * 16;
            aR0 = ldg4_guard(A, m0 + ar,  kb + akq,      M, K);
            aR1 = ldg4_guard(A, m0 + ar,  kb + akq + 4,  M, K);
            bR0 = ldg4_guard(B, kb + bkr, n0 + bnq,      K, N);
            bR1 = ldg4_guard(B, kb + bkr, n0 + bnq + 4,  K, N);
        }

        // ---- MMA over the two k=8 steps (mask-split at fragment load) ----
#pragma unroll
        for (int ks = 0; ks < 2; ks++) {
            const int kk = ks * 8;
            uint32_t ah[4][4], al[4][4], bh[4][2], bl[4][2];
#pragma unroll
            for (int mi = 0; mi < 4; mi++) {
                const int m = warp_m * 64 + mi * 16 + g;
                float x0 = As[cur][kk + tig    ][m    ];
                float x1 = As[cur][kk + tig    ][m + 8];
                float x2 = As[cur][kk + tig + 4][m    ];
                float x3 = As[cur][kk + tig + 4][m + 8];
                uint32_t h0 = tf32_hi_bits(x0), h1 = tf32_hi_bits(x1);
                uint32_t h2 = tf32_hi_bits(x2), h3 = tf32_hi_bits(x3);
                ah[mi][0] = h0; al[mi][0] = __float_as_uint(x0 - __uint_as_float(h0));
                ah[mi][1] = h1; al[mi][1] = __float_as_uint(x1 - __uint_as_float(h1));
                ah[mi][2] = h2; al[mi][2] = __float_as_uint(x2 - __uint_as_float(h2));
                ah[mi][3] = h3; al[mi][3] = __float_as_uint(x3 - __uint_as_float(h3));
            }
#pragma unroll
            for (int ni = 0; ni < 4; ni++) {
                const int n = warp_n * 32 + ni * 8 + g;
                float y0 = Bs[cur][kk + tig    ][n];
                float y1 = Bs[cur][kk + tig + 4][n];
                uint32_t h0 = tf32_hi_bits(y0), h1 = tf32_hi_bits(y1);
                bh[ni][0] = h0; bl[ni][0] = __float_as_uint(y0 - __uint_as_float(h0));
                bh[ni][1] = h1; bl[ni][1] = __float_as_uint(y1 - __uint_as_float(h1));
            }
            // product-major order: consecutive MMAs hit independent accumulators
#pragma unroll
            for (int mi = 0; mi < 4; mi++)
#pragma unroll
                for (int ni = 0; ni < 4; ni++)
                    mma_tf32(acc[mi][ni], ah[mi], bh[ni]);
#pragma unroll
            for (int mi = 0; mi < 4; mi++)
#pragma unroll
                for (int ni = 0; ni < 4; ni++)
                    mma_tf32(acc[mi][ni], ah[mi], bl[ni]);
#pragma unroll
            for (int mi = 0; mi < 4; mi++)
#pragma unroll
                for (int ni = 0; ni < 4; ni++)
                    mma_tf32(acc[mi][ni], al[mi], bh[ni]);
        }

        // ---- stage tile kt+1 into the other buffer ----
        if (more) {
            const int nxt = cur ^ 1;
            float av[8] = {aR0.x, aR0.y, aR0.z, aR0.w, aR1.x, aR1.y, aR1.z, aR1.w};
#pragma unroll
            for (int j = 0; j < 8; j++)
                As[nxt][akq + j][ar] = RELU_A ? fmaxf(av[j], 0.f) : av[j];
            *reinterpret_cast<float4*>(&Bs[nxt][bkr][bnq + 0]) = bR0;
            *reinterpret_cast<float4*>(&Bs[nxt][bkr][bnq + 4]) = bR1;
        }
        __syncthreads();
    }

    // ---- epilogue ----
#pragma unroll
    for (int mi = 0; mi < 4; mi++) {
#pragma unroll
        for (int ni = 0; ni < 4; ni++) {
            const int r  = m0 + warp_m * 64 + mi * 16 + g;
            const int cc = n0 + warp_n * 32 + ni * 8 + 2 * tig;
            if (cc + 1 < N) {
                if (r < M)
                    *reinterpret_cast<float2*>(C + (size_t)r * N + cc) =
                        make_float2(acc[mi][ni][0], acc[mi][ni][1]);
                if (r + 8 < M)
                    *reinterpret_cast<float2*>(C + (size_t)(r + 8) * N + cc) =
                        make_float2(acc[mi][ni][2], acc[mi][ni][3]);
            } else if (cc < N) {
                if (r < M)     C[(size_t)r * N + cc]       = acc[mi][ni][0];
                if (r + 8 < M) C[(size_t)(r + 8) * N + cc] = acc[mi][ni][2];
            }
        }
    }
}

// ===========================================================================
// Zero kernel (vector stores, grid-stride)
// ===========================================================================
__global__ void zero_kernel(float4* __restrict__ p, int n4) {
    int i = blockIdx.x * blockDim.x + threadIdx.x;
    int stride = gridDim.x * blockDim.x;
    float4 z = make_float4(0.f, 0.f, 0.f, 0.f);
    for (; i < n4; i += stride) p[i] = z;
}

// ===========================================================================
// SpMM (COO, vector-red scatter):  out[row[e], :] += vals[e] * sup[col[e], :]
// ===========================================================================
__global__ __launch_bounds__(256) void spmm_wide(
    const int* __restrict__ row, const int* __restrict__ col,
    const float* __restrict__ vals, const float* __restrict__ sup,
    float* __restrict__ out, int D)
{
    int e = blockIdx.x;
    int r = __ldg(row + e);
    int c = __ldg(col + e);
    float v = __ldg(vals + e);
    const float4* s = reinterpret_cast<const float4*>(sup + (size_t)c * D);
    float* o = out + (size_t)r * D;
    int nd4 = D >> 2;
    for (int t = threadIdx.x; t < nd4; t += blockDim.x) {
        float4 x = __ldg(s + t);
        red_add_v4(o + 4 * t, v * x.x, v * x.y, v * x.z, v * x.w);
    }
}

__global__ __launch_bounds__(256) void spmm_narrow(
    const int* __restrict__ row, const int* __restrict__ col,
    const float* __restrict__ vals, const float* __restrict__ sup,
    float* __restrict__ out, int D, int E)
{
    int e = blockIdx.x * (blockDim.x >> 5) + (threadIdx.x >> 5);
    if (e >= E) return;
    int lane = threadIdx.x & 31;
    int r = __ldg(row + e);
    int c = __ldg(col + e);
    float v = __ldg(vals + e);
    const float4* s = reinterpret_cast<const float4*>(sup + (size_t)c * D);
    float* o = out + (size_t)r * D;
    int nd4 = D >> 2;
    for (int t = lane; t < nd4; t += 32) {
        float4 x = __ldg(s + t);
        red_add_v4(o + 4 * t, v * x.x, v * x.y, v * x.z, v * x.w);
    }
}

// ===========================================================================
// Fused relu + row L2-normalize
// ===========================================================================
__global__ __launch_bounds__(256) void l2norm_relu(
    const float* __restrict__ in, float* __restrict__ out, int D)
{
    int r = blockIdx.x;
    const float* x = in + (size_t)r * D;
    float* o = out + (size_t)r * D;

    float s = 0.f;
    for (int t = threadIdx.x; t < D; t += blockDim.x) {
        float v = fmaxf(x[t], 0.f);
        s += v * v;
    }
#pragma unroll
    for (int off = 16; off > 0; off >>= 1)
        s += __shfl_xor_sync(0xFFFFFFFFu, s, off);
    __shared__ float red[8];
    int wid = threadIdx.x >> 5;
    if ((threadIdx.x & 31) == 0) red[wid] = s;
    __syncthreads();
    if (threadIdx.x < 8) {
        float t = red[threadIdx.x];
#pragma unroll
        for (int off = 4; off > 0; off >>= 1)
            t += __shfl_xor_sync(0xFFu, t, off);
        if (threadIdx.x == 0) red[0] = t;
    }
    __syncthreads();
    float inv = 1.f / fmaxf(sqrtf(red[0]), 1e-12f);
    for (int t = threadIdx.x; t < D; t += blockDim.x)
        o[t] = fmaxf(x[t], 0.f) * inv;
}

__global__ void relu_copy(const float* __restrict__ in, float* __restrict__ out, int n) {
    int i = blockIdx.x * blockDim.x + threadIdx.x;
    int stride = gridDim.x * blockDim.x;
    for (; i < n; i += stride) out[i] = fmaxf(in[i], 0.f);
}

// ===========================================================================
// Host-side pipeline
// ===========================================================================
static inline int cdiv(int a, int b) { return (a + b - 1) / b; }
static inline int isqrt_i(int v) { return (int)floor(sqrt((double)v) + 0.5); }

static void run_gemm(const float* A, const float* B, float* C,
                     int M, int N, int K, bool reluA)
{
    dim3 grid(cdiv(N, 128), cdiv(M, 128));
    if (reluA) gemm_mma<true ><<<grid, 256>>>(A, B, C, M, N, K);
    else       gemm_mma<false><<<grid, 256>>>(A, B, C, M, N, K);
}

static void zero_buf(float* p, size_t n) {
    int n4 = (int)(n / 4);
    zero_kernel<<<1024, 256>>>(reinterpret_cast<float4*>(p), n4);
}

extern "C" void kernel_launch(void* const* d_in, const int* in_sizes, int n_in,
                              void* d_out, int out_size)
{
    const float* emb_sr  = (const float*)d_in[0];
    const float* emb_tg  = (const float*)d_in[1];
    const float* attr_sr = (const float*)d_in[2];
    const float* attr_tg = (const float*)d_in[3];
    const int*   row_sr  = (const int*)  d_in[4];
    const int*   col_sr  = (const int*)  d_in[5];
    const float* vals_sr = (const float*)d_in[6];
    const int*   row_tg  = (const int*)  d_in[7];
    const int*   col_tg  = (const int*)  d_in[8];
    const float* vals_tg = (const float*)d_in[9];
    const float* W_s0    = (const float*)d_in[10];
    const float* W_s1    = (const float*)d_in[11];
    const float* W_a11   = (const float*)d_in[12];
    const float* W_a12   = (const float*)d_in[13];
    const float* W_a2    = (const float*)d_in[14];

    const int D  = isqrt_i(in_sizes[10]);          // 1000
    const int Da = isqrt_i(in_sizes[14]);          // 100
    const int A  = in_sizes[12] / Da;              // 1000
    const int N  = in_sizes[0] / D;                // 20000
    const int M  = in_sizes[1] / D;                // 20000
    const int E1 = in_sizes[4];                    // 160000
    const int E2 = in_sizes[7];

    float* sup;  cudaGetSymbolAddress((void**)&sup,  g_sup);
    float* agg;  cudaGetSymbolAddress((void**)&agg,  g_agg);
    float* supA; cudaGetSymbolAddress((void**)&supA, g_supA);
    float* aggA; cudaGetSymbolAddress((void**)&aggA, g_aggA);

    float* out = (float*)d_out;
    float* out_sr  = out;
    float* out_tg  = out + (size_t)N * D;
    float* out_sra = out + (size_t)(N + M) * D;
    float* out_tga = out_sra + (size_t)N * Da;

    // ---------------- structural branch (shared weights W_s0, W_s1) --------
    for (int g = 0; g < 2; g++) {
        const float* emb  = g ? emb_tg : emb_sr;
        const int*   row  = g ? row_tg : row_sr;
        const int*   col  = g ? col_tg : col_sr;
        const float* vals = g ? vals_tg : vals_sr;
        const int    E    = g ? E2 : E1;
        const int    Nn   = g ? M : N;
        float*       op   = g ? out_tg : out_sr;

        // layer 1
        run_gemm(emb, W_s0, sup, Nn, D, D, false);
        zero_buf(agg, (size_t)Nn * D);
        spmm_wide<<<E, 256>>>(row, col, vals, sup, agg, D);
        // layer 2 (relu fused into A-tile load)
        run_gemm(agg, W_s1, sup, Nn, D, D, true);
        zero_buf(agg, (size_t)Nn * D);
        spmm_wide<<<E, 256>>>(row, col, vals, sup, agg, D);
        // relu + l2norm to output
        l2norm_relu<<<Nn, 256>>>(agg, op, D);
    }

    // ---------------- attribute branch ------------------------------------
    for (int g = 0; g < 2; g++) {
        const float* attr = g ? attr_tg : attr_sr;
        const float* Wa1  = g ? W_a12 : W_a11;
        const int*   row  = g ? row_tg : row_sr;
        const int*   col  = g ? col_tg : col_sr;
        const float* vals = g ? vals_tg : vals_sr;
        const int    E    = g ? E2 : E1;
        const int    Nn   = g ? M : N;
        float*       op   = g ? out_tga : out_sra;

        // layer 1: attr[Nn,A] @ Wa1[A,Da]
        run_gemm(attr, Wa1, supA, Nn, Da, A, false);
        zero_buf(aggA, (size_t)Nn * Da);
        spmm_narrow<<<cdiv(E, 8), 256>>>(row, col, vals, supA, aggA, Da, E);
        // layer 2: relu(agg) @ W_a2[Da,Da]
        run_gemm(aggA, W_a2, supA, Nn, Da, Da, true);
        zero_buf(aggA, (size_t)Nn * Da);
        spmm_narrow<<<cdiv(E, 8), 256>>>(row, col, vals, supA, aggA, Da, E);
        // final relu to output
        relu_copy<<<1024, 256>>>(aggA, op, Nn * Da);
    }
}